// round 4
// baseline (speedup 1.0000x reference)
#include <cuda_runtime.h>
#include <math.h>
#include <stdint.h>

// ---------------------------------------------------------------------------
// Shapes (fixed): L=12, E=128, H=4, D=32, F=512, B=64, CIN=256, N=257
// Tokens T = B*N = 16448 = 64 * 257
// ---------------------------------------------------------------------------
#define TOKENS 16448
#define NTOK 257
#define BATCH 64

// scratch (device globals; allocation is forbidden)
__device__ float g_x  [TOKENS * 128];   // residual stream
__device__ float g_h  [TOKENS * 128];   // post-LN
__device__ float g_qkv[TOKENS * 384];
__device__ float g_o  [TOKENS * 128];   // attention output
__device__ float g_ffn[TOKENS * 512];   // ffn hidden

__device__ __forceinline__ float warp_sum(float v) {
    #pragma unroll
    for (int o = 16; o; o >>= 1) v += __shfl_xor_sync(0xffffffffu, v, o);
    return v;
}

__device__ __forceinline__ uint32_t to_tf32(float f) {
    uint32_t u;
    asm("cvt.rna.tf32.f32 %0, %1;" : "=r"(u) : "f"(f));
    return u;
}

// D = A(16x8, row) * B(8x8, col) + D, tf32 in, f32 accum
__device__ __forceinline__ void mma_tf32(float c[4], const uint32_t a[4], const uint32_t b[2]) {
    asm volatile(
        "mma.sync.aligned.m16n8k8.row.col.f32.tf32.tf32.f32 "
        "{%0,%1,%2,%3}, {%4,%5,%6,%7}, {%8,%9}, {%0,%1,%2,%3};"
        : "+f"(c[0]), "+f"(c[1]), "+f"(c[2]), "+f"(c[3])
        : "r"(a[0]), "r"(a[1]), "r"(a[2]), "r"(a[3]), "r"(b[0]), "r"(b[1]));
}

// ---------------------------------------------------------------------------
// Tensor-core GEMM: C[M,N] = A[M,K] @ W[N,K]^T + bias, fused epilogue.
// MODE 0: +bias   MODE 1: gelu(+bias)   MODE 2: +bias + residual
// Block tile 64x128, K-chunk 32. 256 threads = 8 warps in 2x4 (each 32x32).
// ---------------------------------------------------------------------------
#define SK 36   // padded k-stride (bank = (4g+c)%32 -> conflict-free frags)

template <int MODE>
__global__ __launch_bounds__(256)
void gemm_mma(const float* __restrict__ A, const float* __restrict__ W,
              const float* __restrict__ bias, const float* __restrict__ res,
              float* __restrict__ C, int M, int N, int K)
{
    __shared__ uint32_t As[64][SK];
    __shared__ uint32_t Bs[128][SK];
    const int tid = threadIdx.x;
    const int lane = tid & 31, wid = tid >> 5;
    const int warp_m = wid >> 2, warp_n = wid & 3;
    const int m0 = blockIdx.y * 64, n0 = blockIdx.x * 128;
    const int g = lane >> 2, cl = lane & 3;

    float acc[2][4][4];
    #pragma unroll
    for (int i = 0; i < 2; i++)
        #pragma unroll
        for (int j = 0; j < 4; j++)
            #pragma unroll
            for (int r = 0; r < 4; r++) acc[i][j][r] = 0.f;

    for (int k0 = 0; k0 < K; k0 += 32) {
        #pragma unroll
        for (int it = 0; it < 2; it++) {
            int e = tid + it * 256;
            int row = e >> 3, c4 = (e & 7) * 4;
            float4 v = *(const float4*)(A + (size_t)(m0 + row) * K + k0 + c4);
            As[row][c4 + 0] = to_tf32(v.x);
            As[row][c4 + 1] = to_tf32(v.y);
            As[row][c4 + 2] = to_tf32(v.z);
            As[row][c4 + 3] = to_tf32(v.w);
        }
        #pragma unroll
        for (int it = 0; it < 4; it++) {
            int e = tid + it * 256;
            int row = e >> 3, c4 = (e & 7) * 4;
            float4 v = *(const float4*)(W + (size_t)(n0 + row) * K + k0 + c4);
            Bs[row][c4 + 0] = to_tf32(v.x);
            Bs[row][c4 + 1] = to_tf32(v.y);
            Bs[row][c4 + 2] = to_tf32(v.z);
            Bs[row][c4 + 3] = to_tf32(v.w);
        }
        __syncthreads();

        #pragma unroll
        for (int ks = 0; ks < 4; ks++) {
            const int kk = ks * 8;
            uint32_t af[2][4], bf[4][2];
            #pragma unroll
            for (int mt = 0; mt < 2; mt++) {
                int r = warp_m * 32 + mt * 16 + g;
                af[mt][0] = As[r][kk + cl];
                af[mt][1] = As[r + 8][kk + cl];
                af[mt][2] = As[r][kk + 4 + cl];
                af[mt][3] = As[r + 8][kk + 4 + cl];
            }
            #pragma unroll
            for (int nt = 0; nt < 4; nt++) {
                int n = warp_n * 32 + nt * 8 + g;
                bf[nt][0] = Bs[n][kk + cl];
                bf[nt][1] = Bs[n][kk + 4 + cl];
            }
            #pragma unroll
            for (int mt = 0; mt < 2; mt++)
                #pragma unroll
                for (int nt = 0; nt < 4; nt++)
                    mma_tf32(acc[mt][nt], af[mt], bf[nt]);
        }
        __syncthreads();
    }

    #pragma unroll
    for (int mt = 0; mt < 2; mt++) {
        int r = m0 + warp_m * 32 + mt * 16 + g;
        #pragma unroll
        for (int nt = 0; nt < 4; nt++) {
            int n = n0 + warp_n * 32 + nt * 8 + cl * 2;
            float b0 = bias[n], b1 = bias[n + 1];
            float v[4] = {acc[mt][nt][0] + b0, acc[mt][nt][1] + b1,
                          acc[mt][nt][2] + b0, acc[mt][nt][3] + b1};
            if (MODE == 1) {
                #pragma unroll
                for (int i = 0; i < 4; i++)
                    v[i] = v[i] * 0.5f * (1.0f + erff(v[i] * 0.70710678118654752f));
            }
            if (MODE == 2) {
                float2 r0 = *(const float2*)(res + (size_t)r * N + n);
                float2 r1 = *(const float2*)(res + (size_t)(r + 8) * N + n);
                v[0] += r0.x; v[1] += r0.y; v[2] += r1.x; v[3] += r1.y;
            }
            *(float2*)(C + (size_t)r * N + n)       = make_float2(v[0], v[1]);
            *(float2*)(C + (size_t)(r + 8) * N + n) = make_float2(v[2], v[3]);
        }
    }
}

// ---------------------------------------------------------------------------
// Conv 3x3 s2 p1 as implicit GEMM on tensor cores: M=16384, N=128, K=2304.
// ---------------------------------------------------------------------------
__global__ __launch_bounds__(256)
void conv_mma(const float* __restrict__ feat, const float* __restrict__ W,
              const float* __restrict__ cb, const float* __restrict__ pos,
              float* __restrict__ x)
{
    __shared__ uint32_t As[64][SK];
    __shared__ uint32_t Bs[128][SK];
    const int K = 2304;
    const int tid = threadIdx.x;
    const int lane = tid & 31, wid = tid >> 5;
    const int warp_m = wid >> 2, warp_n = wid & 3;
    const int m0 = blockIdx.y * 64;
    const int g = lane >> 2, cl = lane & 3;

    float acc[2][4][4];
    #pragma unroll
    for (int i = 0; i < 2; i++)
        #pragma unroll
        for (int j = 0; j < 4; j++)
            #pragma unroll
            for (int r = 0; r < 4; r++) acc[i][j][r] = 0.f;

    for (int k0 = 0; k0 < K; k0 += 32) {
        #pragma unroll
        for (int it = 0; it < 8; it++) {
            int e = tid + it * 256;
            int ml = e >> 5, kl = e & 31;
            int m = m0 + ml;
            int k = k0 + kl;
            int b = m >> 8, p = m & 255;
            int y = p >> 4, xx = p & 15;
            int c = k / 9, rr = k - c * 9;
            int ky = rr / 3, kx = rr - ky * 3;
            int iy = y * 2 - 1 + ky;
            int ix = xx * 2 - 1 + kx;
            float v = 0.f;
            if (iy >= 0 && iy < 32 && ix >= 0 && ix < 32)
                v = feat[(((size_t)b * 256 + c) * 32 + iy) * 32 + ix];
            As[ml][kl] = to_tf32(v);
        }
        #pragma unroll
        for (int it = 0; it < 4; it++) {
            int e = tid + it * 256;
            int row = e >> 3, c4 = (e & 7) * 4;
            float4 v = *(const float4*)(W + (size_t)row * K + k0 + c4);
            Bs[row][c4 + 0] = to_tf32(v.x);
            Bs[row][c4 + 1] = to_tf32(v.y);
            Bs[row][c4 + 2] = to_tf32(v.z);
            Bs[row][c4 + 3] = to_tf32(v.w);
        }
        __syncthreads();

        #pragma unroll
        for (int ks = 0; ks < 4; ks++) {
            const int kk = ks * 8;
            uint32_t af[2][4], bf[4][2];
            #pragma unroll
            for (int mt = 0; mt < 2; mt++) {
                int r = warp_m * 32 + mt * 16 + g;
                af[mt][0] = As[r][kk + cl];
                af[mt][1] = As[r + 8][kk + cl];
                af[mt][2] = As[r][kk + 4 + cl];
                af[mt][3] = As[r + 8][kk + 4 + cl];
            }
            #pragma unroll
            for (int nt = 0; nt < 4; nt++) {
                int n = warp_n * 32 + nt * 8 + g;
                bf[nt][0] = Bs[n][kk + cl];
                bf[nt][1] = Bs[n][kk + 4 + cl];
            }
            #pragma unroll
            for (int mt = 0; mt < 2; mt++)
                #pragma unroll
                for (int nt = 0; nt < 4; nt++)
                    mma_tf32(acc[mt][nt], af[mt], bf[nt]);
        }
        __syncthreads();
    }

    #pragma unroll
    for (int mt = 0; mt < 2; mt++) {
        int r = m0 + warp_m * 32 + mt * 16 + g;
        #pragma unroll
        for (int rr = 0; rr < 2; rr++) {
            int m = r + rr * 8;
            int b = m >> 8, p = m & 255;
            float* dst = x + ((size_t)b * NTOK + p + 1) * 128;
            const float* pp = pos + (size_t)(p + 1) * 128;
            #pragma unroll
            for (int nt = 0; nt < 4; nt++) {
                int n = warp_n * 32 + nt * 8 + cl * 2;
                float v0 = acc[mt][nt][rr * 2 + 0] + cb[n] + pp[n];
                float v1 = acc[mt][nt][rr * 2 + 1] + cb[n + 1] + pp[n + 1];
                *(float2*)(dst + n) = make_float2(v0, v1);
            }
        }
    }
}

// cls token rows: x[b,0,:] = cls + pos[0]
__global__ void cls_kernel(const float* __restrict__ cls,
                           const float* __restrict__ pos, float* __restrict__ x)
{
    int b = blockIdx.x, e = threadIdx.x;
    x[(size_t)b * NTOK * 128 + e] = cls[e] + pos[e];
}

// ---------------------------------------------------------------------------
// LayerNorm over E=128: 1 warp per token, float4 lanes.
// ---------------------------------------------------------------------------
__global__ __launch_bounds__(256)
void ln_kernel(const float* __restrict__ x, float* __restrict__ h,
               const float* __restrict__ s, const float* __restrict__ b, float eps)
{
    int tok = blockIdx.x * 8 + (threadIdx.x >> 5);
    int lane = threadIdx.x & 31;
    if (tok >= TOKENS) return;
    const float4* xr = (const float4*)(x + (size_t)tok * 128);
    float4 v = xr[lane];
    float mean = warp_sum(v.x + v.y + v.z + v.w) * (1.f / 128.f);
    float dx = v.x - mean, dy = v.y - mean, dz = v.z - mean, dw = v.w - mean;
    float var = warp_sum(dx * dx + dy * dy + dz * dz + dw * dw) * (1.f / 128.f);
    float rstd = rsqrtf(var + eps);
    float4 sv = ((const float4*)s)[lane];
    float4 bv = ((const float4*)b)[lane];
    float4 o;
    o.x = dx * rstd * sv.x + bv.x;
    o.y = dy * rstd * sv.y + bv.y;
    o.z = dz * rstd * sv.z + bv.z;
    o.w = dw * rstd * sv.w + bv.w;
    ((float4*)(h + (size_t)tok * 128))[lane] = o;
}

// ---------------------------------------------------------------------------
// Flash attention on tensor cores. Block per (b,h), 9 warps; warp owns a
// 32-query tile; keys in 9 chunks of 32 with online softmax.
// QK: plain tf32 (score magnitudes small -> error negligible).
// PV: hi/lo split  P*V ~= Phi*Vhi + Phi*Vlo + Plo*Vhi  (near-fp32 exact).
// smem strides 36 / 292 keep all fragment LDS bank-conflict-free.
// ---------------------------------------------------------------------------
#define ASA 36
#define ASV 292
#define OFF_QP 10368            // 288*36
#define OFF_VH 20736
#define OFF_VL 30080            // + 32*292
#define OFF_PL 39424
#define ATT_SMEM ((OFF_PL + 10368) * 4)   // 199168 B

__global__ __launch_bounds__(288, 1)
void attn_mma(const float* __restrict__ qkv, float* __restrict__ o)
{
    extern __shared__ uint32_t smw[];
    uint32_t* Ks = smw;                 // [288][36] tf32 K
    uint32_t* QP = smw + OFF_QP;        // [288][36] tf32 Q, then per-warp P_hi
    uint32_t* Vh = smw + OFF_VH;        // [32][292] tf32 V^T hi
    uint32_t* Vl = smw + OFF_VL;        // [32][292] tf32 V^T lo
    uint32_t* Pl = smw + OFF_PL;        // [288][36] per-warp P_lo

    const int b = blockIdx.x, h = blockIdx.y;
    const int tid = threadIdx.x, w = tid >> 5, lane = tid & 31;
    const int g = lane >> 2, cl = lane & 3;
    const float* base = qkv + (size_t)b * NTOK * 384 + h * 32;

    // load Q,K,V (rows >= 257 zero-padded)
    for (int i = tid; i < 288 * 32; i += 288) {
        int row = i >> 5, d = i & 31;
        float qv = 0.f, kv = 0.f, vv = 0.f;
        if (row < NTOK) {
            const float* p = base + (size_t)row * 384;
            qv = p[d]; kv = p[128 + d]; vv = p[256 + d];
        }
        Ks[row * ASA + d] = to_tf32(kv);
        QP[row * ASA + d] = to_tf32(qv);
        uint32_t vh = to_tf32(vv);
        Vh[d * ASV + row] = vh;
        Vl[d * ASV + row] = to_tf32(vv - __uint_as_float(vh));
    }
    __syncthreads();

    // hoist Q fragments (warp reads only its own 32 rows)
    const int q0 = w * 32;
    uint32_t aq[2][4][4];
    #pragma unroll
    for (int mt = 0; mt < 2; mt++)
        #pragma unroll
        for (int ks = 0; ks < 4; ks++) {
            int r = q0 + mt * 16 + g;
            aq[mt][ks][0] = QP[r * ASA + ks * 8 + cl];
            aq[mt][ks][1] = QP[(r + 8) * ASA + ks * 8 + cl];
            aq[mt][ks][2] = QP[r * ASA + ks * 8 + cl + 4];
            aq[mt][ks][3] = QP[(r + 8) * ASA + ks * 8 + cl + 4];
        }
    __syncwarp();
    uint32_t* Phi = QP + q0 * ASA;      // reuse this warp's Q rows for P_hi
    uint32_t* Plo = Pl + q0 * ASA;

    float acc[2][4][4];
    #pragma unroll
    for (int mt = 0; mt < 2; mt++)
        #pragma unroll
        for (int nt = 0; nt < 4; nt++)
            #pragma unroll
            for (int r = 0; r < 4; r++) acc[mt][nt][r] = 0.f;
    float mrun[2][2] = {{-1e30f, -1e30f}, {-1e30f, -1e30f}};
    float lrun[2][2] = {{0.f, 0.f}, {0.f, 0.f}};
    const float scale = 0.17677669529663687f;   // 1/sqrt(32)

    for (int c = 0; c < 9; c++) {
        const int k0 = c * 32;
        float s[2][4][4];
        #pragma unroll
        for (int mt = 0; mt < 2; mt++)
            #pragma unroll
            for (int nt = 0; nt < 4; nt++)
                #pragma unroll
                for (int r = 0; r < 4; r++) s[mt][nt][r] = 0.f;

        // S = Q K^T  (chunk of 32 keys)
        #pragma unroll
        for (int ks = 0; ks < 4; ks++) {
            uint32_t bk[4][2];
            #pragma unroll
            for (int nt = 0; nt < 4; nt++) {
                int kr = k0 + nt * 8 + g;
                bk[nt][0] = Ks[kr * ASA + ks * 8 + cl];
                bk[nt][1] = Ks[kr * ASA + ks * 8 + cl + 4];
            }
            #pragma unroll
            for (int mt = 0; mt < 2; mt++)
                #pragma unroll
                for (int nt = 0; nt < 4; nt++)
                    mma_tf32(s[mt][nt], aq[mt][ks], bk[nt]);
        }

        // scale + mask invalid keys
        #pragma unroll
        for (int mt = 0; mt < 2; mt++)
            #pragma unroll
            for (int nt = 0; nt < 4; nt++)
                #pragma unroll
                for (int r = 0; r < 4; r++) {
                    int key = k0 + nt * 8 + 2 * cl + (r & 1);
                    float v = s[mt][nt][r] * scale;
                    s[mt][nt][r] = (key < NTOK) ? v : -1e30f;
                }

        // online softmax (per row-half), write P hi/lo to smem
        #pragma unroll
        for (int mt = 0; mt < 2; mt++)
            #pragma unroll
            for (int rh = 0; rh < 2; rh++) {
                float mx = -1e30f;
                #pragma unroll
                for (int nt = 0; nt < 4; nt++) {
                    mx = fmaxf(mx, s[mt][nt][2 * rh]);
                    mx = fmaxf(mx, s[mt][nt][2 * rh + 1]);
                }
                mx = fmaxf(mx, __shfl_xor_sync(0xffffffffu, mx, 1));
                mx = fmaxf(mx, __shfl_xor_sync(0xffffffffu, mx, 2));
                float mnew = fmaxf(mrun[mt][rh], mx);
                float alpha = __expf(mrun[mt][rh] - mnew);
                mrun[mt][rh] = mnew;
                lrun[mt][rh] *= alpha;
                #pragma unroll
                for (int nt = 0; nt < 4; nt++) {
                    acc[mt][nt][2 * rh] *= alpha;
                    acc[mt][nt][2 * rh + 1] *= alpha;
                }
                float psum = 0.f;
                int row = mt * 16 + rh * 8 + g;
                #pragma unroll
                for (int nt = 0; nt < 4; nt++) {
                    float p0 = __expf(s[mt][nt][2 * rh] - mnew);
                    float p1 = __expf(s[mt][nt][2 * rh + 1] - mnew);
                    psum += p0 + p1;
                    int col = nt * 8 + 2 * cl;
                    uint32_t h0 = to_tf32(p0), h1 = to_tf32(p1);
                    Phi[row * ASA + col]     = h0;
                    Phi[row * ASA + col + 1] = h1;
                    Plo[row * ASA + col]     = to_tf32(p0 - __uint_as_float(h0));
                    Plo[row * ASA + col + 1] = to_tf32(p1 - __uint_as_float(h1));
                }
                lrun[mt][rh] += psum;
            }
        __syncwarp();

        // acc += P * V (hi/lo split)
        #pragma unroll
        for (int ks = 0; ks < 4; ks++) {
            uint32_t ah[2][4], al[2][4], bh[4][2], bl[4][2];
            #pragma unroll
            for (int mt = 0; mt < 2; mt++) {
                int r = mt * 16 + g;
                ah[mt][0] = Phi[r * ASA + ks * 8 + cl];
                ah[mt][1] = Phi[(r + 8) * ASA + ks * 8 + cl];
                ah[mt][2] = Phi[r * ASA + ks * 8 + cl + 4];
                ah[mt][3] = Phi[(r + 8) * ASA + ks * 8 + cl + 4];
                al[mt][0] = Plo[r * ASA + ks * 8 + cl];
                al[mt][1] = Plo[(r + 8) * ASA + ks * 8 + cl];
                al[mt][2] = Plo[r * ASA + ks * 8 + cl + 4];
                al[mt][3] = Plo[(r + 8) * ASA + ks * 8 + cl + 4];
            }
            #pragma unroll
            for (int nt = 0; nt < 4; nt++) {
                int d = nt * 8 + g;
                int m = k0 + ks * 8;
                bh[nt][0] = Vh[d * ASV + m + cl];
                bh[nt][1] = Vh[d * ASV + m + cl + 4];
                bl[nt][0] = Vl[d * ASV + m + cl];
                bl[nt][1] = Vl[d * ASV + m + cl + 4];
            }
            #pragma unroll
            for (int mt = 0; mt < 2; mt++)
                #pragma unroll
                for (int nt = 0; nt < 4; nt++) {
                    mma_tf32(acc[mt][nt], ah[mt], bh[nt]);
                    mma_tf32(acc[mt][nt], ah[mt], bl[nt]);
                    mma_tf32(acc[mt][nt], al[mt], bh[nt]);
                }
        }
        __syncwarp();
    }

    // normalize + store
    #pragma unroll
    for (int mt = 0; mt < 2; mt++)
        #pragma unroll
        for (int rh = 0; rh < 2; rh++) {
            float l = lrun[mt][rh];
            l += __shfl_xor_sync(0xffffffffu, l, 1);
            l += __shfl_xor_sync(0xffffffffu, l, 2);
            float inv = 1.f / l;
            int q = q0 + mt * 16 + rh * 8 + g;
            if (q < NTOK) {
                float* dst = o + ((size_t)b * NTOK + q) * 128 + h * 32;
                #pragma unroll
                for (int nt = 0; nt < 4; nt++) {
                    int d = nt * 8 + 2 * cl;
                    *(float2*)(dst + d) =
                        make_float2(acc[mt][nt][2 * rh] * inv,
                                    acc[mt][nt][2 * rh + 1] * inv);
                }
            }
        }
}

// ---------------------------------------------------------------------------
// Head: final LN (eps 1e-6) on token 0 of each batch, out_feat + fc.
// ---------------------------------------------------------------------------
__global__ __launch_bounds__(128)
void head_kernel(const float* __restrict__ x, const float* __restrict__ fns,
                 const float* __restrict__ fnb, const float* __restrict__ fcw,
                 const float* __restrict__ fcb, float* __restrict__ out)
{
    __shared__ float red[4];
    __shared__ float fsh[128];
    int b = blockIdx.x, t = threadIdx.x, w = t >> 5, lane = t & 31;
    float v = x[(size_t)b * NTOK * 128 + t];

    float s = warp_sum(v);
    if (lane == 0) red[w] = s;
    __syncthreads();
    float mean = (red[0] + red[1] + red[2] + red[3]) * (1.f / 128.f);
    __syncthreads();
    float d = v - mean;
    float sq = warp_sum(d * d);
    if (lane == 0) red[w] = sq;
    __syncthreads();
    float var = (red[0] + red[1] + red[2] + red[3]) * (1.f / 128.f);
    float rstd = rsqrtf(var + 1e-6f);
    float f = d * rstd * fns[t] + fnb[t];
    out[128 + (size_t)b * 128 + t] = f;
    fsh[t] = f;
    __syncthreads();
    if (t < 2) {
        float a = fcb[t];
        for (int e = 0; e < 128; e++) a += fsh[e] * fcw[t * 128 + e];
        out[b * 2 + t] = a;
    }
}

// ---------------------------------------------------------------------------
extern "C" void kernel_launch(void* const* d_in, const int* in_sizes, int n_in,
                              void* d_out, int out_size)
{
    const float* feat    = (const float*)d_in[0];
    const float* conv_w  = (const float*)d_in[1];
    const float* conv_b  = (const float*)d_in[2];
    const float* pos_emb = (const float*)d_in[3];
    const float* cls_tok = (const float*)d_in[4];
    const float* ln1_s   = (const float*)d_in[5];
    const float* ln1_b   = (const float*)d_in[6];
    const float* qkv_w   = (const float*)d_in[7];
    const float* qkv_b   = (const float*)d_in[8];
    const float* proj_w  = (const float*)d_in[9];
    const float* proj_b  = (const float*)d_in[10];
    const float* ln2_s   = (const float*)d_in[11];
    const float* ln2_b   = (const float*)d_in[12];
    const float* ffn1_w  = (const float*)d_in[13];
    const float* ffn1_b  = (const float*)d_in[14];
    const float* ffn2_w  = (const float*)d_in[15];
    const float* ffn2_b  = (const float*)d_in[16];
    const float* fn_s    = (const float*)d_in[17];
    const float* fn_b    = (const float*)d_in[18];
    const float* fc_w    = (const float*)d_in[19];
    const float* fc_b    = (const float*)d_in[20];
    float* out = (float*)d_out;

    float *px, *ph, *pq, *po, *pf;
    cudaGetSymbolAddress((void**)&px, g_x);
    cudaGetSymbolAddress((void**)&ph, g_h);
    cudaGetSymbolAddress((void**)&pq, g_qkv);
    cudaGetSymbolAddress((void**)&po, g_o);
    cudaGetSymbolAddress((void**)&pf, g_ffn);

    cudaFuncSetAttribute(attn_mma, cudaFuncAttributeMaxDynamicSharedMemorySize, ATT_SMEM);

    cls_kernel<<<BATCH, 128>>>(cls_tok, pos_emb, px);
    conv_mma<<<dim3(1, 256), 256>>>(feat, conv_w, conv_b, pos_emb, px);

    for (int l = 0; l < 12; l++) {
        ln_kernel<<<TOKENS / 8, 256>>>(px, ph, ln1_s + l * 128, ln1_b + l * 128, 1e-5f);
        gemm_mma<0><<<dim3(3, 257), 256>>>(
            ph, qkv_w + (size_t)l * 384 * 128, qkv_b + l * 384, nullptr, pq,
            TOKENS, 384, 128);
        attn_mma<<<dim3(BATCH, 4), 288, ATT_SMEM>>>(pq, po);
        gemm_mma<2><<<dim3(1, 257), 256>>>(
            po, proj_w + (size_t)l * 128 * 128, proj_b + l * 128, px, px,
            TOKENS, 128, 128);
        ln_kernel<<<TOKENS / 8, 256>>>(px, ph, ln2_s + l * 128, ln2_b + l * 128, 1e-5f);
        gemm_mma<1><<<dim3(4, 257), 256>>>(
            ph, ffn1_w + (size_t)l * 512 * 128, ffn1_b + l * 512, nullptr, pf,
            TOKENS, 512, 128);
        gemm_mma<2><<<dim3(1, 257), 256>>>(
            pf, ffn2_w + (size_t)l * 128 * 512, ffn2_b + l * 128, px, px,
            TOKENS, 128, 512);
    }

    head_kernel<<<BATCH, 128>>>(px, fn_s, fn_b, fc_w, fc_b, out);
}